// round 4
// baseline (speedup 1.0000x reference)
#include <cuda_runtime.h>
#include <math.h>

#define NROWS 65536
#define DDIM  64
#define KCODES 512
#define COMMIT 0.25f

// ---------------- scratch (no allocations allowed) ----------------
__device__ float  g_wnorm[KCODES];           // 0.5 * ||w_k||^2
__device__ float  g_wT[KCODES * DDIM];       // w transposed: [k][d]
__device__ int    g_counts[KCODES];
__device__ double g_sumsq;

// ---------------- helpers ----------------
__device__ __forceinline__ unsigned int f2ord(float f) {
    unsigned int u = __float_as_uint(f);
    return (u & 0x80000000u) ? ~u : (u | 0x80000000u);
}
__device__ __forceinline__ void ffma2(unsigned long long& d,
                                      unsigned long long a,
                                      unsigned long long b) {
    asm("fma.rn.f32x2 %0, %1, %2, %0;" : "+l"(d) : "l"(a), "l"(b));
}
__device__ __forceinline__ unsigned long long pk2(float lo, float hi) {
    unsigned long long r;
    asm("mov.b64 %0, {%1, %2};" : "=l"(r) : "f"(lo), "f"(hi));
    return r;
}
__device__ __forceinline__ void upk2(unsigned long long v, float& lo, float& hi) {
    asm("mov.b64 {%0, %1}, %2;" : "=f"(lo), "=f"(hi) : "l"(v));
}

// ---------------- kernel 0: reset + wnorm + W transpose ----------------
__global__ void vq_prep_kernel(const float* __restrict__ w) {
    int k = threadIdx.x;              // 512 threads, one per code
    g_counts[k] = 0;
    if (k == 0) g_sumsq = 0.0;
    float s = 0.f;
    #pragma unroll
    for (int d = 0; d < DDIM; d++) {
        float v = w[d * KCODES + k];  // coalesced across k
        s += v * v;
        g_wT[k * DDIM + d] = v;       // contiguous per-code row for gather
    }
    g_wnorm[k] = 0.5f * s;
}

// ---------------- kernel 1: fused argmax + gather + loss partials ----------
// 1024 blocks x 128 threads. Block tile = 64 rows x all 512 codes
// (looped in 64-col chunks). Thread microtile: 8 rows x 4 cols as 16 packed
// f32x2 accumulators. W duplicated in smem -> one LDS.64 yields a broadcast
// (v,v) pair. Epilogue (X tile still resident) emits quantized/sumsq/idx.
#define BROWS 64
#define XPITCH 68                              // 64 rows + 4 pad
#define SM_X_BYTES   (DDIM * XPITCH * 4)       // 17408
#define SM_W_OFF     SM_X_BYTES                // Wdup: [64][64] float2 = 32768
#define SM_SWN_OFF   (SM_W_OFF + DDIM * 64 * 8)        // 50176
#define SM_BEST_OFF  (SM_SWN_OFF + 256)                // 50432
#define SM_SK_OFF    (SM_BEST_OFF + BROWS * 8)         // 50944
#define SM_TOTAL     (SM_SK_OFF + BROWS * 4)           // 51200

__global__ __launch_bounds__(128) void vq_argmin_kernel(
    const float* __restrict__ x, float* __restrict__ out, int out_size,
    const float* __restrict__ w)
{
    extern __shared__ unsigned char sm[];
    float*  XsT = (float*)sm;                                  // [d][68] (64 used)
    float2* Wd  = (float2*)(sm + SM_W_OFF);                    // [d][64] duplicated
    float*  swn = (float*)(sm + SM_SWN_OFF);                   // [64]
    unsigned long long* best = (unsigned long long*)(sm + SM_BEST_OFF); // [64]
    int*    sk  = (int*)(sm + SM_SK_OFF);                      // [64] chosen codes

    const int tid  = threadIdx.x;       // 0..127
    const int row0 = blockIdx.x * BROWS;
    const int tr = tid >> 4;            // 0..7  : rows tr*8 .. tr*8+7
    const int tc = tid & 15;            // 0..15 : cols tc + 16*j (bank-spread)

    // load X tile transposed (coalesced global reads along d)
    #pragma unroll
    for (int i = tid; i < BROWS * DDIM; i += 128) {
        int r = i >> 6, d = i & 63;
        XsT[d * XPITCH + r] = x[(row0 + r) * DDIM + d];
    }
    if (tid < BROWS) best[tid] = 0ULL;

    float bestv[8];
    int   bestk[8];
    #pragma unroll
    for (int i = 0; i < 8; i++) { bestv[i] = -INFINITY; bestk[i] = 0; }

    for (int kc = 0; kc < KCODES; kc += 64) {
        __syncthreads();
        // load W chunk duplicated: Wd[d][kl] = (v, v)
        #pragma unroll
        for (int i = tid; i < DDIM * 64; i += 128) {
            int d = i >> 6, kl = i & 63;
            float v = w[d * KCODES + kc + kl];
            Wd[d * 64 + kl] = make_float2(v, v);
        }
        if (tid < 64) swn[tid] = g_wnorm[kc + tid];
        __syncthreads();

        unsigned long long acc[4][4];
        #pragma unroll
        for (int p = 0; p < 4; p++)
            #pragma unroll
            for (int j = 0; j < 4; j++) acc[p][j] = 0ULL;

        #pragma unroll 8
        for (int d = 0; d < DDIM; d++) {
            const float* xr = XsT + d * XPITCH + tr * 8;
            float4 a = *(const float4*)xr;        // rows +0..3
            float4 b = *(const float4*)(xr + 4);  // rows +4..7
            unsigned long long xp0 = pk2(a.x, a.y);
            unsigned long long xp1 = pk2(a.z, a.w);
            unsigned long long xp2 = pk2(b.x, b.y);
            unsigned long long xp3 = pk2(b.z, b.w);
            const unsigned long long* wr =
                (const unsigned long long*)(Wd + d * 64);
            #pragma unroll
            for (int j = 0; j < 4; j++) {
                unsigned long long wb = wr[tc + 16 * j];  // broadcast (v,v)
                ffma2(acc[0][j], xp0, wb);
                ffma2(acc[1][j], xp1, wb);
                ffma2(acc[2][j], xp2, wb);
                ffma2(acc[3][j], xp3, wb);
            }
        }

        // fold chunk into running per-row best (strict > keeps lowest k)
        #pragma unroll
        for (int j = 0; j < 4; j++) {
            int   kg = kc + tc + 16 * j;
            float wn = swn[tc + 16 * j];
            #pragma unroll
            for (int p = 0; p < 4; p++) {
                float lo, hi;
                upk2(acc[p][j], lo, hi);
                float slo = lo - wn, shi = hi - wn;
                if (slo > bestv[2 * p])     { bestv[2 * p]     = slo; bestk[2 * p]     = kg; }
                if (shi > bestv[2 * p + 1]) { bestv[2 * p + 1] = shi; bestk[2 * p + 1] = kg; }
            }
        }
    }
    __syncthreads();
    // cross-thread per-row reduction: (ordered score | inverted idx)
    #pragma unroll
    for (int i = 0; i < 8; i++) {
        int r = tr * 8 + i;
        unsigned long long key =
            ((unsigned long long)f2ord(bestv[i]) << 32) |
            (unsigned long long)(unsigned)(KCODES - 1 - bestk[i]);
        atomicMax(&best[r], key);
    }
    __syncthreads();

    const long long idx_off = (long long)NROWS * DDIM + 2;
    const bool write_q   = (out_size >= (long long)NROWS * DDIM);
    const bool write_idx = (out_size >= idx_off + NROWS);

    if (tid < BROWS) {
        int k = KCODES - 1 - (int)(best[tid] & 0xFFFFFFFFu);
        sk[tid] = k;
        atomicAdd(&g_counts[k], 1);
        if (write_idx) out[idx_off + row0 + tid] = (float)k;
    }
    __syncthreads();

    // fused gather: X tile is resident; wT rows are contiguous (L2-hot).
    // 128 threads -> 2 rows x 64 dims per iteration, coalesced loads+stores.
    float partial = 0.f;
    if (write_q) {
        const int d  = tid & 63;
        const int rh = tid >> 6;             // 0 or 1
        #pragma unroll 4
        for (int r2 = 0; r2 < BROWS; r2 += 2) {
            int r = r2 + rh;
            int k = sk[r];
            float q  = g_wT[k * DDIM + d];
            float xv = XsT[d * XPITCH + r];
            out[(long long)(row0 + r) * DDIM + d] = q;   // quantized_st == quantized
            float df = q - xv;
            partial += df * df;
        }
    }
    #pragma unroll
    for (int o = 16; o > 0; o >>= 1)
        partial += __shfl_down_sync(0xFFFFFFFFu, partial, o);
    if ((tid & 31) == 0) atomicAdd(&g_sumsq, (double)partial);
}

// ---------------- kernel 2: loss + perplexity ----------------
__global__ void vq_final_kernel(float* __restrict__ out, int out_size) {
    __shared__ float red[512];
    int t = threadIdx.x;
    float p = (float)g_counts[t] * (1.0f / (float)NROWS);
    red[t] = p * logf(p + 1e-10f);
    __syncthreads();
    for (int s = 256; s > 0; s >>= 1) {
        if (t < s) red[t] += red[t + s];
        __syncthreads();
    }
    if (t == 0) {
        long long base = (long long)NROWS * DDIM;
        if (out_size >= base + 2) {
            double mse = g_sumsq / (double)((long long)NROWS * DDIM);
            out[base]     = (float)((1.0 + (double)COMMIT) * mse);  // q + 0.25*e
            out[base + 1] = expf(-red[0]);
        }
    }
}

// ---------------- launch ----------------
extern "C" void kernel_launch(void* const* d_in, const int* in_sizes, int n_in,
                              void* d_out, int out_size) {
    const float* x = (const float*)d_in[0];   // [65536, 64]
    const float* w = (const float*)d_in[1];   // [64, 512]
    float* out = (float*)d_out;

    cudaFuncSetAttribute(vq_argmin_kernel,
                         cudaFuncAttributeMaxDynamicSharedMemorySize, SM_TOTAL);

    vq_prep_kernel<<<1, 512>>>(w);
    vq_argmin_kernel<<<NROWS / BROWS, 128, SM_TOTAL>>>(x, out, out_size, w);
    vq_final_kernel<<<1, 512>>>(out, out_size);
}